// round 3
// baseline (speedup 1.0000x reference)
#include <cuda_runtime.h>
#include <cstdint>

#define EMB      128
#define NRAD     16
#define N_ATOMS_ 100000
#define N_EDGES_ 1000000
#define N_ELEM   95
#define TILE     128
#define NTILES   ((N_EDGES_ + TILE - 1) / TILE)   // 7813
#define GRID_MAIN 148
#define THREADS  256

// ---------------- smem layout (bytes) ----------------
// A: rbf_e in fragment-major layout: [kstep(16)][row(128)][8 floats], 32B chunks,
//    chunk half-swap swizzle keyed on row bit2. 64KB.
#define OFF_A     0
// B: W3^T same layout keyed on n. 64KB.
#define OFF_B     65536
#define OFF_WRBF  131072                    // W_rbf [16][128] f32, 8KB
#define OFF_BIAS  (OFF_WRBF + 8192)         // b_rbf [128]
#define OFF_ZI    (OFF_BIAS + 512)
#define OFF_ZJ    (OFF_ZI + 512)
#define OFF_RBF   (OFF_ZJ + 512)            // rbf tile [128][20] padded, 10240B
#define SMEM_TOTAL (OFF_RBF + 10240)

__device__ float g_EW1[N_ELEM * EMB];
__device__ float g_EW2[N_ELEM * EMB];

// ---------------- helpers ----------------
__device__ __forceinline__ float to_tf32(float x) {
    uint32_t u;
    asm("cvt.rna.tf32.f32 %0, %1;" : "=r"(u) : "f"(x));
    return __uint_as_float(u);
}

// fast silu for the inner activation (feeds a 128-term averaged dot product)
__device__ __forceinline__ float silu_tanh(float x) {
    float t;
    asm("tanh.approx.f32 %0, %1;" : "=f"(t) : "f"(0.5f * x));
    return 0.5f * x * (1.0f + t);
}

// precise silu for the final output
__device__ __forceinline__ float silu_exact(float x) {
    return __fdividef(x, 1.0f + __expf(-x));
}

// tf32 mma: D(16x8) += A(16x8) * B(8x8)
__device__ __forceinline__ void mma_tf32(float* d, const uint32_t* a, uint32_t b0, uint32_t b1) {
    asm volatile(
        "mma.sync.aligned.m16n8k8.row.col.f32.tf32.tf32.f32 "
        "{%0,%1,%2,%3}, {%4,%5,%6,%7}, {%8,%9}, {%0,%1,%2,%3};"
        : "+f"(d[0]), "+f"(d[1]), "+f"(d[2]), "+f"(d[3])
        : "r"(a[0]), "r"(a[1]), "r"(a[2]), "r"(a[3]), "r"(b0), "r"(b1));
}

// position of col k (0..7) inside a chunk: pairs (c, c+4) made adjacent
__device__ __forceinline__ int posmap(int k) { return 2 * (k & 3) + (k >> 2); }

// ---------------- precompute: EW1 = emb@W1 + b, EW2 = emb@W2 ----------------
__global__ void prep_kernel(const float* __restrict__ emb, const float* __restrict__ W,
                            const float* __restrict__ b) {
    int z = blockIdx.x, n = threadIdx.x;
    const float* er = emb + z * EMB;
    float s1 = b[n], s2 = 0.0f;
#pragma unroll 8
    for (int k = 0; k < EMB; k++) {
        float ev = er[k];
        s1 += ev * W[k * EMB + n];
        s2 += ev * W[(EMB + k) * EMB + n];
    }
    g_EW1[z * EMB + n] = s1;
    g_EW2[z * EMB + n] = s2;
}

// ---------------- x_0 = embeddings[Z] ----------------
__global__ void x0_kernel(const int* __restrict__ Z, const float* __restrict__ emb,
                          float* __restrict__ out0) {
    int i = blockIdx.x * blockDim.x + threadIdx.x;
    if (i >= N_ATOMS_ * (EMB / 4)) return;
    int a = i >> 5, q = i & 31;
    ((float4*)out0)[(size_t)a * 32 + q] = ((const float4*)emb)[(size_t)Z[a] * 32 + q];
}

// ---------------- main fused edge kernel ----------------
__global__ void __launch_bounds__(THREADS, 1)
main_kernel(const int* __restrict__ Z, const float* __restrict__ rbf,
            const int* __restrict__ idx_i, const int* __restrict__ idx_j,
            const float* __restrict__ W_rbf, const float* __restrict__ b_rbf,
            const float* __restrict__ W, float* __restrict__ out) {
    extern __shared__ char smem[];
    const int tid = threadIdx.x;
    const int wid = tid >> 5, lane = tid & 31;
    const int q = lane >> 2, c = lane & 3;          // quad layout inside warp
    const int m0 = (wid & 3) * 32;                  // warp's GEMM2 row base
    const int n0 = (wid >> 2) * 64;                 // warp's GEMM2 col base

    // --- one-time fills: B (W3^T tf32, fragment-major swizzled), W_rbf, bias ---
    for (int idx = tid; idx < EMB * EMB; idx += THREADS) {
        int n = idx & 127, k = idx >> 7;                          // coalesced over n
        float v = to_tf32(W[(2 * EMB + k) * EMB + n]);            // W3[k][n]
        int phys = posmap(k & 7) ^ (((n >> 2) & 1) << 2);
        *(float*)(smem + OFF_B + (((k >> 3) * 128 + n) << 5) + (phys << 2)) = v;
    }
    for (int idx = tid; idx < NRAD * EMB; idx += THREADS)
        ((float*)(smem + OFF_WRBF))[idx] = W_rbf[idx];
    if (tid < EMB) ((float*)(smem + OFF_BIAS))[tid] = b_rbf[tid];
    __syncthreads();

    const int m  = tid & 127;                // phase-A row
    const int c0 = (tid >> 7) * 64;          // phase-A col half

    for (int t = blockIdx.x; t < NTILES; t += gridDim.x) {
        const long base = (long)t * TILE;

        // --- stage: zi/zj gather + rbf tile -> smem (coalesced) ---
        {
            long e = base + m; if (e >= N_EDGES_) e = N_EDGES_ - 1;
            if (tid < TILE) ((int*)(smem + OFF_ZI))[m] = Z[idx_i[e]];
            else            ((int*)(smem + OFF_ZJ))[m] = Z[idx_j[e]];
        }
        for (int i = tid; i < 512; i += THREADS) {               // 128 rows x 4 float4
            int rrow = i >> 2, qd = i & 3;
            long e = base + rrow; if (e >= N_EDGES_) e = N_EDGES_ - 1;
            float4 v = ((const float4*)rbf)[e * 4 + qd];
            *(float4*)(smem + OFF_RBF + rrow * 80 + qd * 16) = v;
        }
        __syncthreads();

        // --- phase A: rbf_e[m, c0..c0+63] = silu(rbf[m]@W_rbf + b) -> A smem (tf32) ---
        {
            const float* rr = (const float*)(smem + OFF_RBF + m * 80);
            float rv[16];
#pragma unroll
            for (int i2 = 0; i2 < 4; i2++) {
                float4 v = *(const float4*)(rr + 4 * i2);
                rv[4 * i2] = v.x; rv[4 * i2 + 1] = v.y; rv[4 * i2 + 2] = v.z; rv[4 * i2 + 3] = v.w;
            }
            float acc[64];
            const float* bs = (const float*)(smem + OFF_BIAS) + c0;
#pragma unroll
            for (int j = 0; j < 64; j += 4) {
                float4 bb = *(const float4*)(bs + j);
                acc[j] = bb.x; acc[j + 1] = bb.y; acc[j + 2] = bb.z; acc[j + 3] = bb.w;
            }
            const float* wr = (const float*)(smem + OFF_WRBF);
#pragma unroll
            for (int r = 0; r < 16; r++) {
                float a = rv[r];
                const float4* wrow = (const float4*)(wr + r * EMB + c0);  // warp-broadcast
#pragma unroll
                for (int j = 0; j < 64; j += 4) {
                    float4 w4 = wrow[j >> 2];
                    acc[j]     += a * w4.x;
                    acc[j + 1] += a * w4.y;
                    acc[j + 2] += a * w4.z;
                    acc[j + 3] += a * w4.w;
                }
            }
            // store into fragment-major A layout: chunk (ks, m), 8 cols permuted + swizzled
            const int ksb = c0 >> 3;
            const int sw = (m >> 2) & 1;
#pragma unroll
            for (int i2 = 0; i2 < 8; i2++) {
                float buf[8];
#pragma unroll
                for (int k = 0; k < 8; k++)
                    buf[posmap(k)] = to_tf32(silu_tanh(acc[i2 * 8 + k]));
                float4 lo = make_float4(buf[0], buf[1], buf[2], buf[3]);
                float4 hi = make_float4(buf[4], buf[5], buf[6], buf[7]);
                float4* dst = (float4*)(smem + OFF_A + (((ksb + i2) * 128 + m) << 5));
                dst[0] = sw ? hi : lo;
                dst[1] = sw ? lo : hi;
            }
        }
        __syncthreads();

        // --- GEMM2: D[128,128] = rbf_e @ W3, tf32 mma.sync, acc in registers ---
        float dacc[2][8][4];
#pragma unroll
        for (int mt = 0; mt < 2; mt++)
#pragma unroll
            for (int nt = 0; nt < 8; nt++)
#pragma unroll
                for (int r = 0; r < 4; r++) dacc[mt][nt][r] = 0.0f;

#pragma unroll 4
        for (int ks = 0; ks < 16; ks++) {
            uint32_t a[2][4];
#pragma unroll
            for (int mt = 0; mt < 2; mt++) {
                int r = m0 + mt * 16 + q;
                int swo = (((r >> 2) & 1) << 4);                 // 16B half swap
                const char* pa = smem + OFF_A + ((ks * 128 + r) << 5) + (((2 * c) << 2) ^ swo);
                uint2 v_lo = *(const uint2*)pa;                  // row r:   a0 (k=c), a2 (k=c+4)
                uint2 v_hi = *(const uint2*)(pa + 256);          // row r+8: a1, a3
                a[mt][0] = v_lo.x; a[mt][2] = v_lo.y;
                a[mt][1] = v_hi.x; a[mt][3] = v_hi.y;
            }
#pragma unroll
            for (int nt = 0; nt < 8; nt++) {
                int n = n0 + nt * 8 + q;
                int swb = (((n >> 2) & 1) << 4);
                uint2 bv = *(const uint2*)(smem + OFF_B + ((ks * 128 + n) << 5) + (((2 * c) << 2) ^ swb));
                mma_tf32(dacc[0][nt], a[0], bv.x, bv.y);
                mma_tf32(dacc[1][nt], a[1], bv.x, bv.y);
            }
        }

        // --- epilogue: out = silu(D + EW1[zi] + EW2[zj]) ---
        const int* zi_s = (const int*)(smem + OFF_ZI);
        const int* zj_s = (const int*)(smem + OFF_ZJ);
#pragma unroll
        for (int mt = 0; mt < 2; mt++) {
#pragma unroll
            for (int sub = 0; sub < 2; sub++) {
                int r = m0 + mt * 16 + sub * 8 + q;
                long e = base + r;
                if (e < N_EDGES_) {
                    int zi = zi_s[r], zj = zj_s[r];
                    const float* p1 = g_EW1 + zi * EMB;
                    const float* p2 = g_EW2 + zj * EMB;
                    float* op = out + (size_t)e * EMB;
#pragma unroll
                    for (int nt = 0; nt < 8; nt++) {
                        int n = n0 + nt * 8 + 2 * c;
                        float2 w1 = *(const float2*)(p1 + n);
                        float2 w2 = *(const float2*)(p2 + n);
                        float2 o;
                        o.x = silu_exact(dacc[mt][nt][sub * 2 + 0] + w1.x + w2.x);
                        o.y = silu_exact(dacc[mt][nt][sub * 2 + 1] + w1.y + w2.y);
                        *(float2*)(op + n) = o;
                    }
                }
            }
        }
        __syncthreads();   // protect smem (A, rbf_s, zi/zj) before next tile overwrites
    }
}

// ---------------- launch ----------------
extern "C" void kernel_launch(void* const* d_in, const int* in_sizes, int n_in,
                              void* d_out, int out_size) {
    (void)in_sizes; (void)n_in; (void)out_size;
    const int*   Z     = (const int*)d_in[0];
    const float* rbf   = (const float*)d_in[1];
    const int*   idx_i = (const int*)d_in[2];
    const int*   idx_j = (const int*)d_in[3];
    const float* emb   = (const float*)d_in[4];
    const float* W_rbf = (const float*)d_in[5];
    const float* b_rbf = (const float*)d_in[6];
    const float* W     = (const float*)d_in[7];
    const float* b     = (const float*)d_in[8];
    float* out  = (float*)d_out;
    float* out0 = out + (size_t)N_EDGES_ * EMB;

    prep_kernel<<<N_ELEM, EMB>>>(emb, W, b);
    x0_kernel<<<(N_ATOMS_ * (EMB / 4) + 255) / 256, 256>>>(Z, emb, out0);
    cudaFuncSetAttribute(main_kernel, cudaFuncAttributeMaxDynamicSharedMemorySize, SMEM_TOTAL);
    main_kernel<<<GRID_MAIN, THREADS, SMEM_TOTAL>>>(Z, rbf, idx_i, idx_j, W_rbf, b_rbf, W, out);
}

// round 4
// speedup vs baseline: 1.5390x; 1.5390x over previous
#include <cuda_runtime.h>
#include <cuda_fp16.h>
#include <cstdint>

#define EMB      128
#define NRAD     16
#define N_ATOMS_ 100000
#define N_EDGES_ 1000000
#define N_ELEM   95
#define TILE     128
#define NTILES   ((N_EDGES_ + TILE - 1) / TILE)   // 7813
#define GRID_MAIN 148
#define THREADS  256

// ---------------- smem layout (bytes) ----------------
// BT2: W3^T fp16 B-fragment layout [ks(8)][n(128)][16 halfs permuted] = 32KB
// BT1: W_rbf^T fp16 same per-chunk layout [n(128)][16 halfs]          = 4KB
// RBFH: rbf tile fp16 A-fragment layout [row(128)][16 halfs]          = 4KB
#define OFF_BT2   0
#define OFF_BT1   32768
#define OFF_RBFH  36864
#define OFF_BIAS  40960
#define OFF_ZI    41472
#define OFF_ZJ    41984
#define SMEM_TOTAL 42496

__device__ float g_EW1[N_ELEM * EMB];
__device__ float g_EW2[N_ELEM * EMB];

// ---------------- helpers ----------------
// fast silu (1 MUFU): x*sigmoid(x) = 0.5*x*(1+tanh(x/2))
__device__ __forceinline__ float silu_tanh(float x) {
    float t;
    asm("tanh.approx.f32 %0, %1;" : "=f"(t) : "f"(0.5f * x));
    return 0.5f * x * (1.0f + t);
}
// precise silu for final output
__device__ __forceinline__ float silu_exact(float x) {
    return __fdividef(x, 1.0f + __expf(-x));
}

__device__ __forceinline__ uint32_t pack2(float lo, float hi) {
    uint32_t r;
    asm("cvt.rn.f16x2.f32 %0, %1, %2;" : "=r"(r) : "f"(hi), "f"(lo));
    return r;
}

// fp16 mma m16n8k16, fp32 accum, in-place on d
__device__ __forceinline__ void mma_f16(float* d,
    uint32_t a0, uint32_t a1, uint32_t a2, uint32_t a3,
    uint32_t b0, uint32_t b1) {
    asm volatile(
        "mma.sync.aligned.m16n8k16.row.col.f32.f16.f16.f32 "
        "{%0,%1,%2,%3}, {%4,%5,%6,%7}, {%8,%9}, {%0,%1,%2,%3};"
        : "+f"(d[0]), "+f"(d[1]), "+f"(d[2]), "+f"(d[3])
        : "r"(a0), "r"(a1), "r"(a2), "r"(a3), "r"(b0), "r"(b1));
}

// physical half position inside a 16-half (32B) chunk so thread c's uint2 at
// byte 8c holds halfs {2c, 2c+1, 2c+8, 2c+9} (== mma fragment pairs)
__device__ __forceinline__ int physmap(int kk) {
    return 4 * ((kk & 7) >> 1) + 2 * (kk >> 3) + (kk & 1);
}

// ---------------- precompute: EW1 = emb@W1 + b, EW2 = emb@W2 ----------------
__global__ void prep_kernel(const float* __restrict__ emb, const float* __restrict__ W,
                            const float* __restrict__ b) {
    __shared__ float p1[EMB], p2[EMB];
    int z = blockIdx.x, n = threadIdx.x & 127, h = threadIdx.x >> 7;
    const float* er = emb + z * EMB;
    float s1 = 0.0f, s2 = 0.0f;
    int k0 = h * 64;
#pragma unroll 8
    for (int k = k0; k < k0 + 64; k++) {
        float ev = er[k];
        s1 += ev * W[k * EMB + n];
        s2 += ev * W[(EMB + k) * EMB + n];
    }
    if (h) { p1[n] = s1; p2[n] = s2; }
    __syncthreads();
    if (!h) {
        g_EW1[z * EMB + n] = s1 + p1[n] + b[n];
        g_EW2[z * EMB + n] = s2 + p2[n];
    }
}

// ---------------- x_0 = embeddings[Z] ----------------
__global__ void x0_kernel(const int* __restrict__ Z, const float* __restrict__ emb,
                          float* __restrict__ out0) {
    int i = blockIdx.x * blockDim.x + threadIdx.x;
    if (i >= N_ATOMS_ * (EMB / 4)) return;
    int a = i >> 5, q = i & 31;
    ((float4*)out0)[(size_t)a * 32 + q] = ((const float4*)emb)[(size_t)Z[a] * 32 + q];
}

// ---------------- main fused edge kernel ----------------
__global__ void __launch_bounds__(THREADS, 1)
main_kernel(const int* __restrict__ Z, const float* __restrict__ rbf,
            const int* __restrict__ idx_i, const int* __restrict__ idx_j,
            const float* __restrict__ W_rbf, const float* __restrict__ b_rbf,
            const float* __restrict__ W, float* __restrict__ out) {
    __shared__ char smem[SMEM_TOTAL];
    const int tid  = threadIdx.x;
    const int wid  = tid >> 5, lane = tid & 31;
    const int q    = lane >> 2, c = lane & 3;
    const int m0   = (wid & 3) * 32;     // warp row base (4 m-quarters)
    const int n0   = (wid >> 2) * 64;    // warp col base (2 n-halves)

    // ---- one-time fills ----
    // BT1: W_rbf^T fp16 fragments
    for (int idx = tid; idx < EMB * NRAD; idx += THREADS) {
        int n = idx & 127, k = idx >> 7;                       // coalesced over n
        __half h = __float2half(W_rbf[k * EMB + n]);
        *(unsigned short*)(smem + OFF_BT1 + n * 32 + physmap(k) * 2) = __half_as_ushort(h);
    }
    // BT2: W3^T fp16 fragments
    for (int idx = tid; idx < EMB * EMB; idx += THREADS) {
        int n = idx & 127, k = idx >> 7;
        __half h = __float2half(W[(2 * EMB + k) * EMB + n]);   // W3[k][n]
        int ks = k >> 4, kk = k & 15;
        *(unsigned short*)(smem + OFF_BT2 + ks * 4096 + n * 32 + physmap(kk) * 2) =
            __half_as_ushort(h);
    }
    if (tid < EMB) ((float*)(smem + OFF_BIAS))[tid] = b_rbf[tid];
    __syncthreads();

    for (int t = blockIdx.x; t < NTILES; t += gridDim.x) {
        const long base = (long)t * TILE;

        // ---- stage: species ids + rbf tile (fp16 fragment layout) ----
        {
            int mm = tid & 127;
            long e = base + mm; if (e >= N_EDGES_) e = N_EDGES_ - 1;
            if (tid < TILE) ((int*)(smem + OFF_ZI))[mm] = Z[idx_i[e]];
            else            ((int*)(smem + OFF_ZJ))[mm] = Z[idx_j[e]];
        }
        if (tid < TILE) {
            long e = base + tid; if (e >= N_EDGES_) e = N_EDGES_ - 1;
            const float4* rp = (const float4*)(rbf + e * NRAD);
            float4 f0 = rp[0], f1 = rp[1], f2 = rp[2], f3 = rp[3];
            float v[16] = {f0.x, f0.y, f0.z, f0.w, f1.x, f1.y, f1.z, f1.w,
                           f2.x, f2.y, f2.z, f2.w, f3.x, f3.y, f3.z, f3.w};
            uint32_t o[8];
#pragma unroll
            for (int cc = 0; cc < 4; cc++) {
                o[2 * cc]     = pack2(v[2 * cc],     v[2 * cc + 1]);
                o[2 * cc + 1] = pack2(v[2 * cc + 8], v[2 * cc + 9]);
            }
            uint4* dst = (uint4*)(smem + OFF_RBFH + tid * 32);
            dst[0] = make_uint4(o[0], o[1], o[2], o[3]);
            dst[1] = make_uint4(o[4], o[5], o[6], o[7]);
        }
        __syncthreads();

        // ---- GEMM1 (rbf@W_rbf+b, K=16, one HMMA per n-tile) -> silu -> A frags in regs ----
        uint32_t afrag[2][8][4];
        {
            uint2 arlo[2], arhi[2];
#pragma unroll
            for (int mt = 0; mt < 2; mt++) {
                int r = m0 + 16 * mt + q;
                arlo[mt] = *(const uint2*)(smem + OFF_RBFH + r * 32 + 8 * c);
                arhi[mt] = *(const uint2*)(smem + OFF_RBFH + (r + 8) * 32 + 8 * c);
            }
            const float* bias_s = (const float*)(smem + OFF_BIAS);
#pragma unroll
            for (int nt1 = 0; nt1 < 16; nt1++) {
                uint2 bv = *(const uint2*)(smem + OFF_BT1 + (8 * nt1 + q) * 32 + 8 * c);
                float2 bb = *(const float2*)(bias_s + 8 * nt1 + 2 * c);
#pragma unroll
                for (int mt = 0; mt < 2; mt++) {
                    float d[4] = {bb.x, bb.y, bb.x, bb.y};
                    mma_f16(d, arlo[mt].x, arhi[mt].x, arlo[mt].y, arhi[mt].y, bv.x, bv.y);
                    uint32_t lo = pack2(silu_tanh(d[0]), silu_tanh(d[1]));  // rows q
                    uint32_t hi = pack2(silu_tanh(d[2]), silu_tanh(d[3]));  // rows q+8
                    int ks = nt1 >> 1;
                    if ((nt1 & 1) == 0) { afrag[mt][ks][0] = lo; afrag[mt][ks][1] = hi; }
                    else                { afrag[mt][ks][2] = lo; afrag[mt][ks][3] = hi; }
                }
            }
        }

        // ---- GEMM2: D[128,128] = rbf_e @ W3, fp16 mma, acc fp32 in regs ----
        float dacc[2][8][4];
#pragma unroll
        for (int mt = 0; mt < 2; mt++)
#pragma unroll
            for (int nt = 0; nt < 8; nt++)
#pragma unroll
                for (int r = 0; r < 4; r++) dacc[mt][nt][r] = 0.0f;

#pragma unroll
        for (int ks = 0; ks < 8; ks++) {
#pragma unroll
            for (int nt = 0; nt < 8; nt++) {
                uint2 bv = *(const uint2*)(smem + OFF_BT2 + ks * 4096 +
                                           (n0 + 8 * nt + q) * 32 + 8 * c);
                mma_f16(dacc[0][nt], afrag[0][ks][0], afrag[0][ks][1],
                        afrag[0][ks][2], afrag[0][ks][3], bv.x, bv.y);
                mma_f16(dacc[1][nt], afrag[1][ks][0], afrag[1][ks][1],
                        afrag[1][ks][2], afrag[1][ks][3], bv.x, bv.y);
            }
        }

        // ---- epilogue: out = silu(D + EW1[zi] + EW2[zj]) ----
        const int* zi_s = (const int*)(smem + OFF_ZI);
        const int* zj_s = (const int*)(smem + OFF_ZJ);
#pragma unroll
        for (int mt = 0; mt < 2; mt++) {
#pragma unroll
            for (int sub = 0; sub < 2; sub++) {
                int r = m0 + 16 * mt + 8 * sub + q;
                long e = base + r;
                if (e < N_EDGES_) {
                    int zi = zi_s[r], zj = zj_s[r];
                    const float* p1 = g_EW1 + zi * EMB;
                    const float* p2 = g_EW2 + zj * EMB;
                    float* op = out + (size_t)e * EMB;
#pragma unroll
                    for (int nt = 0; nt < 8; nt++) {
                        int n = n0 + 8 * nt + 2 * c;
                        float2 w1 = *(const float2*)(p1 + n);
                        float2 w2 = *(const float2*)(p2 + n);
                        float2 o;
                        o.x = silu_exact(dacc[mt][nt][2 * sub + 0] + w1.x + w2.x);
                        o.y = silu_exact(dacc[mt][nt][2 * sub + 1] + w1.y + w2.y);
                        *(float2*)(op + n) = o;
                    }
                }
            }
        }
        __syncthreads();   // protect rbfh/zi/zj before next tile overwrites
    }
}

// ---------------- launch ----------------
extern "C" void kernel_launch(void* const* d_in, const int* in_sizes, int n_in,
                              void* d_out, int out_size) {
    (void)in_sizes; (void)n_in; (void)out_size;
    const int*   Z     = (const int*)d_in[0];
    const float* rbf   = (const float*)d_in[1];
    const int*   idx_i = (const int*)d_in[2];
    const int*   idx_j = (const int*)d_in[3];
    const float* emb   = (const float*)d_in[4];
    const float* W_rbf = (const float*)d_in[5];
    const float* b_rbf = (const float*)d_in[6];
    const float* W     = (const float*)d_in[7];
    const float* b     = (const float*)d_in[8];
    float* out  = (float*)d_out;
    float* out0 = out + (size_t)N_EDGES_ * EMB;

    prep_kernel<<<N_ELEM, 256>>>(emb, W, b);
    x0_kernel<<<(N_ATOMS_ * (EMB / 4) + 255) / 256, 256>>>(Z, emb, out0);
    main_kernel<<<GRID_MAIN, THREADS>>>(Z, rbf, idx_i, idx_j, W_rbf, b_rbf, W, out);
}

// round 5
// speedup vs baseline: 2.5431x; 1.6524x over previous
#include <cuda_runtime.h>
#include <cuda_fp16.h>
#include <cstdint>

#define EMB      128
#define NRAD     16
#define N_ATOMS_ 100000
#define N_EDGES_ 1000000
#define N_ELEM   95
#define TILE     128
#define NTILES   ((N_EDGES_ + TILE - 1) / TILE)   // 7813
#define GRID_MAIN 296
#define THREADS  256

// ---------------- smem layout (bytes) ----------------
// BT2: W3^T fp16 B-fragment layout [ks(8)][n(128)][16 halfs permuted] = 32KB
// BT1: W_rbf^T fp16 same per-chunk layout [n(128)][16 halfs]          = 4KB
// RBFH: rbf tile fp16 A-fragment layout [row(128)][16 halfs]          = 4KB
#define OFF_BT2   0
#define OFF_BT1   32768
#define OFF_RBFH  36864
#define OFF_BIAS  40960
#define OFF_ZI    41472
#define OFF_ZJ    41984
#define SMEM_TOTAL 42496

__device__ float g_EW1[N_ELEM * EMB];
__device__ float g_EW2[N_ELEM * EMB];

// ---------------- helpers ----------------
// fast silu (1 MUFU): x*sigmoid(x) = 0.5*x*(1+tanh(x/2))
__device__ __forceinline__ float silu_tanh(float x) {
    float t;
    asm("tanh.approx.f32 %0, %1;" : "=f"(t) : "f"(0.5f * x));
    return 0.5f * x * (1.0f + t);
}
// precise silu for final output
__device__ __forceinline__ float silu_exact(float x) {
    return __fdividef(x, 1.0f + __expf(-x));
}

__device__ __forceinline__ uint32_t pack2(float lo, float hi) {
    uint32_t r;
    asm("cvt.rn.f16x2.f32 %0, %1, %2;" : "=r"(r) : "f"(hi), "f"(lo));
    return r;
}

// fp16 mma m16n8k16, fp32 accum, in-place on d
__device__ __forceinline__ void mma_f16(float* d,
    uint32_t a0, uint32_t a1, uint32_t a2, uint32_t a3,
    uint32_t b0, uint32_t b1) {
    asm volatile(
        "mma.sync.aligned.m16n8k16.row.col.f32.f16.f16.f32 "
        "{%0,%1,%2,%3}, {%4,%5,%6,%7}, {%8,%9}, {%0,%1,%2,%3};"
        : "+f"(d[0]), "+f"(d[1]), "+f"(d[2]), "+f"(d[3])
        : "r"(a0), "r"(a1), "r"(a2), "r"(a3), "r"(b0), "r"(b1));
}

// physical half position inside a 16-half (32B) chunk so thread c's uint2 at
// byte 8c holds halfs {2c, 2c+1, 2c+8, 2c+9} (== mma fragment pairs)
__device__ __forceinline__ int physmap(int kk) {
    return 4 * ((kk & 7) >> 1) + 2 * (kk >> 3) + (kk & 1);
}

// ---------------- precompute: EW1 = emb@W1 + b, EW2 = emb@W2 ----------------
__global__ void prep_kernel(const float* __restrict__ emb, const float* __restrict__ W,
                            const float* __restrict__ b) {
    __shared__ float p1[EMB], p2[EMB];
    int z = blockIdx.x, n = threadIdx.x & 127, h = threadIdx.x >> 7;
    const float* er = emb + z * EMB;
    float s1 = 0.0f, s2 = 0.0f;
    int k0 = h * 64;
#pragma unroll 8
    for (int k = k0; k < k0 + 64; k++) {
        float ev = er[k];
        s1 += ev * W[k * EMB + n];
        s2 += ev * W[(EMB + k) * EMB + n];
    }
    if (h) { p1[n] = s1; p2[n] = s2; }
    __syncthreads();
    if (!h) {
        g_EW1[z * EMB + n] = s1 + p1[n] + b[n];
        g_EW2[z * EMB + n] = s2 + p2[n];
    }
}

// ---------------- x_0 = embeddings[Z] ----------------
__global__ void x0_kernel(const int* __restrict__ Z, const float* __restrict__ emb,
                          float* __restrict__ out0) {
    int i = blockIdx.x * blockDim.x + threadIdx.x;
    if (i >= N_ATOMS_ * (EMB / 4)) return;
    int a = i >> 5, q = i & 31;
    ((float4*)out0)[(size_t)a * 32 + q] = ((const float4*)emb)[(size_t)Z[a] * 32 + q];
}

// ---------------- main fused edge kernel ----------------
__global__ void __launch_bounds__(THREADS, 2)
main_kernel(const int* __restrict__ Z, const float* __restrict__ rbf,
            const int* __restrict__ idx_i, const int* __restrict__ idx_j,
            const float* __restrict__ W_rbf, const float* __restrict__ b_rbf,
            const float* __restrict__ W, float* __restrict__ out) {
    __shared__ char smem[SMEM_TOTAL];
    const int tid  = threadIdx.x;
    const int wid  = tid >> 5, lane = tid & 31;
    const int q    = lane >> 2, c = lane & 3;
    const int m0   = (wid & 3) * 32;     // warp row base (4 m-quarters)
    const int n0   = (wid >> 2) * 64;    // warp col base (2 n-halves)

    // ---- one-time fills ----
    for (int idx = tid; idx < EMB * NRAD; idx += THREADS) {
        int n = idx & 127, k = idx >> 7;                       // coalesced over n
        __half h = __float2half(W_rbf[k * EMB + n]);
        *(unsigned short*)(smem + OFF_BT1 + n * 32 + physmap(k) * 2) = __half_as_ushort(h);
    }
    for (int idx = tid; idx < EMB * EMB; idx += THREADS) {
        int n = idx & 127, k = idx >> 7;
        __half h = __float2half(W[(2 * EMB + k) * EMB + n]);   // W3[k][n]
        int ks = k >> 4, kk = k & 15;
        *(unsigned short*)(smem + OFF_BT2 + ks * 4096 + n * 32 + physmap(kk) * 2) =
            __half_as_ushort(h);
    }
    if (tid < EMB) ((float*)(smem + OFF_BIAS))[tid] = b_rbf[tid];
    __syncthreads();

    for (int t = blockIdx.x; t < NTILES; t += gridDim.x) {
        const long base = (long)t * TILE;

        // ---- stage: species ids + rbf tile (fp16 fragment layout) ----
        {
            int mm = tid & 127;
            long e = base + mm; if (e >= N_EDGES_) e = N_EDGES_ - 1;
            if (tid < TILE) ((int*)(smem + OFF_ZI))[mm] = Z[idx_i[e]];
            else            ((int*)(smem + OFF_ZJ))[mm] = Z[idx_j[e]];
        }
        if (tid < TILE) {
            long e = base + tid; if (e >= N_EDGES_) e = N_EDGES_ - 1;
            const float4* rp = (const float4*)(rbf + e * NRAD);
            float4 f0 = rp[0], f1 = rp[1], f2 = rp[2], f3 = rp[3];
            float v[16] = {f0.x, f0.y, f0.z, f0.w, f1.x, f1.y, f1.z, f1.w,
                           f2.x, f2.y, f2.z, f2.w, f3.x, f3.y, f3.z, f3.w};
            uint32_t o[8];
#pragma unroll
            for (int cc = 0; cc < 4; cc++) {
                o[2 * cc]     = pack2(v[2 * cc],     v[2 * cc + 1]);
                o[2 * cc + 1] = pack2(v[2 * cc + 8], v[2 * cc + 9]);
            }
            uint4* dst = (uint4*)(smem + OFF_RBFH + tid * 32);
            dst[0] = make_uint4(o[0], o[1], o[2], o[3]);
            dst[1] = make_uint4(o[4], o[5], o[6], o[7]);
        }
        __syncthreads();

        // ---- A operands for GEMM1 (rbf fragments, reused for all k-steps) ----
        uint2 arlo[2], arhi[2];
#pragma unroll
        for (int mt = 0; mt < 2; mt++) {
            int r = m0 + 16 * mt + q;
            arlo[mt] = *(const uint2*)(smem + OFF_RBFH + r * 32 + 8 * c);
            arhi[mt] = *(const uint2*)(smem + OFF_RBFH + (r + 8) * 32 + 8 * c);
        }

        // ---- fused GEMM1 -> silu -> GEMM2, k-step at a time (low reg pressure) ----
        float dacc[2][8][4];
#pragma unroll
        for (int mt = 0; mt < 2; mt++)
#pragma unroll
            for (int nt = 0; nt < 8; nt++)
#pragma unroll
                for (int r = 0; r < 4; r++) dacc[mt][nt][r] = 0.0f;

        const float* bias_s = (const float*)(smem + OFF_BIAS);
#pragma unroll
        for (int ks = 0; ks < 8; ks++) {
            uint32_t afrag[2][4];
#pragma unroll
            for (int half = 0; half < 2; half++) {
                int nt1 = 2 * ks + half;
                uint2 bv = *(const uint2*)(smem + OFF_BT1 + (8 * nt1 + q) * 32 + 8 * c);
                float2 bb = *(const float2*)(bias_s + 8 * nt1 + 2 * c);
#pragma unroll
                for (int mt = 0; mt < 2; mt++) {
                    float d[4] = {bb.x, bb.y, bb.x, bb.y};
                    mma_f16(d, arlo[mt].x, arhi[mt].x, arlo[mt].y, arhi[mt].y, bv.x, bv.y);
                    afrag[mt][2 * half]     = pack2(silu_tanh(d[0]), silu_tanh(d[1]));
                    afrag[mt][2 * half + 1] = pack2(silu_tanh(d[2]), silu_tanh(d[3]));
                }
            }
#pragma unroll
            for (int nt = 0; nt < 8; nt++) {
                uint2 bv = *(const uint2*)(smem + OFF_BT2 + ks * 4096 +
                                           (n0 + 8 * nt + q) * 32 + 8 * c);
                mma_f16(dacc[0][nt], afrag[0][0], afrag[0][1], afrag[0][2], afrag[0][3],
                        bv.x, bv.y);
                mma_f16(dacc[1][nt], afrag[1][0], afrag[1][1], afrag[1][2], afrag[1][3],
                        bv.x, bv.y);
            }
        }

        // ---- epilogue: out = silu(D + EW1[zi] + EW2[zj]) ----
        const int* zi_s = (const int*)(smem + OFF_ZI);
        const int* zj_s = (const int*)(smem + OFF_ZJ);
#pragma unroll
        for (int mt = 0; mt < 2; mt++) {
#pragma unroll
            for (int sub = 0; sub < 2; sub++) {
                int r = m0 + 16 * mt + 8 * sub + q;
                long e = base + r;
                if (e < N_EDGES_) {
                    int zi = zi_s[r], zj = zj_s[r];
                    const float* p1 = g_EW1 + zi * EMB;
                    const float* p2 = g_EW2 + zj * EMB;
                    float* op = out + (size_t)e * EMB;
#pragma unroll
                    for (int nt = 0; nt < 8; nt++) {
                        int n = n0 + 8 * nt + 2 * c;
                        float2 w1 = *(const float2*)(p1 + n);
                        float2 w2 = *(const float2*)(p2 + n);
                        float2 o;
                        o.x = silu_exact(dacc[mt][nt][2 * sub + 0] + w1.x + w2.x);
                        o.y = silu_exact(dacc[mt][nt][2 * sub + 1] + w1.y + w2.y);
                        *(float2*)(op + n) = o;
                    }
                }
            }
        }
        __syncthreads();   // protect rbfh/zi/zj before next tile overwrites
    }
}

// ---------------- launch ----------------
extern "C" void kernel_launch(void* const* d_in, const int* in_sizes, int n_in,
                              void* d_out, int out_size) {
    (void)in_sizes; (void)n_in; (void)out_size;
    const int*   Z     = (const int*)d_in[0];
    const float* rbf   = (const float*)d_in[1];
    const int*   idx_i = (const int*)d_in[2];
    const int*   idx_j = (const int*)d_in[3];
    const float* emb   = (const float*)d_in[4];
    const float* W_rbf = (const float*)d_in[5];
    const float* b_rbf = (const float*)d_in[6];
    const float* W     = (const float*)d_in[7];
    const float* b     = (const float*)d_in[8];
    float* out  = (float*)d_out;
    float* out0 = out + (size_t)N_EDGES_ * EMB;

    prep_kernel<<<N_ELEM, 256>>>(emb, W, b);
    x0_kernel<<<(N_ATOMS_ * (EMB / 4) + 255) / 256, 256>>>(Z, emb, out0);
    main_kernel<<<GRID_MAIN, THREADS>>>(Z, rbf, idx_i, idx_j, W_rbf, b_rbf, W, out);
}

// round 6
// speedup vs baseline: 2.7008x; 1.0620x over previous
#include <cuda_runtime.h>
#include <cuda_fp16.h>
#include <cstdint>

#define EMB      128
#define NRAD     16
#define N_ATOMS_ 100000
#define N_EDGES_ 1000000
#define N_ELEM   95
#define TILE     128
#define NTILES   ((N_EDGES_ + TILE - 1) / TILE)   // 7813
#define GRID_MAIN 296
#define THREADS  256

// ---------------- smem layout (bytes) ----------------
// BT2:  W3^T fp16 B-fragment layout [ks(8)][n(128)][16 halfs permuted] = 32KB
// BT1:  W_rbf^T fp16 per-chunk layout [n(128)][16 halfs]               = 4KB
// RBFH: rbf tile fp16 A-fragment layout, DOUBLE buffered               = 2x4KB
// ZI/ZJ: species ids, DOUBLE buffered                                  = 2x512 each
#define OFF_BT2   0
#define OFF_BT1   32768
#define OFF_RBFH  36864
#define OFF_BIAS  45056
#define OFF_ZI    45568
#define OFF_ZJ    46592
#define SMEM_TOTAL 47616

__device__ float g_EW1[N_ELEM * EMB];
__device__ float g_EW2[N_ELEM * EMB];

// ---------------- helpers ----------------
__device__ __forceinline__ float silu_tanh(float x) {
    float t;
    asm("tanh.approx.f32 %0, %1;" : "=f"(t) : "f"(0.5f * x));
    return 0.5f * x * (1.0f + t);
}
__device__ __forceinline__ float silu_exact(float x) {
    return __fdividef(x, 1.0f + __expf(-x));
}
__device__ __forceinline__ uint32_t pack2(float lo, float hi) {
    uint32_t r;
    asm("cvt.rn.f16x2.f32 %0, %1, %2;" : "=r"(r) : "f"(hi), "f"(lo));
    return r;
}
__device__ __forceinline__ void mma_f16(float* d,
    uint32_t a0, uint32_t a1, uint32_t a2, uint32_t a3,
    uint32_t b0, uint32_t b1) {
    asm volatile(
        "mma.sync.aligned.m16n8k16.row.col.f32.f16.f16.f32 "
        "{%0,%1,%2,%3}, {%4,%5,%6,%7}, {%8,%9}, {%0,%1,%2,%3};"
        : "+f"(d[0]), "+f"(d[1]), "+f"(d[2]), "+f"(d[3])
        : "r"(a0), "r"(a1), "r"(a2), "r"(a3), "r"(b0), "r"(b1));
}
// physical half position inside a 16-half (32B) chunk so thread c's uint2 at
// byte 8c holds halfs {2c, 2c+1, 2c+8, 2c+9} (== mma fragment pairs)
__device__ __forceinline__ int physmap(int kk) {
    return 4 * ((kk & 7) >> 1) + 2 * (kk >> 3) + (kk & 1);
}

// ---------------- precompute: EW1 = emb@W1 + b, EW2 = emb@W2 ----------------
__global__ void prep_kernel(const float* __restrict__ emb, const float* __restrict__ W,
                            const float* __restrict__ b) {
    __shared__ float p1[EMB], p2[EMB];
    int z = blockIdx.x, n = threadIdx.x & 127, h = threadIdx.x >> 7;
    const float* er = emb + z * EMB;
    float s1 = 0.0f, s2 = 0.0f;
    int k0 = h * 64;
#pragma unroll 8
    for (int k = k0; k < k0 + 64; k++) {
        float ev = er[k];
        s1 += ev * W[k * EMB + n];
        s2 += ev * W[(EMB + k) * EMB + n];
    }
    if (h) { p1[n] = s1; p2[n] = s2; }
    __syncthreads();
    if (!h) {
        g_EW1[z * EMB + n] = s1 + p1[n] + b[n];
        g_EW2[z * EMB + n] = s2 + p2[n];
    }
}

// ---------------- x_0 = embeddings[Z] ----------------
__global__ void x0_kernel(const int* __restrict__ Z, const float* __restrict__ emb,
                          float* __restrict__ out0) {
    int i = blockIdx.x * blockDim.x + threadIdx.x;
    if (i >= N_ATOMS_ * (EMB / 4)) return;
    int a = i >> 5, q = i & 31;
    ((float4*)out0)[(size_t)a * 32 + q] = ((const float4*)emb)[(size_t)Z[a] * 32 + q];
}

// ---------------- main fused edge kernel ----------------
__global__ void __launch_bounds__(THREADS, 2)
main_kernel(const int* __restrict__ Z, const float* __restrict__ rbf,
            const int* __restrict__ idx_i, const int* __restrict__ idx_j,
            const float* __restrict__ W_rbf, const float* __restrict__ b_rbf,
            const float* __restrict__ W, float* __restrict__ out) {
    __shared__ char smem[SMEM_TOTAL];
    const int tid  = threadIdx.x;
    const int wid  = tid >> 5, lane = tid & 31;
    const int q    = lane >> 2, c = lane & 3;
    const int m0   = (wid & 3) * 32;     // warp row base
    const int n0   = (wid >> 2) * 64;    // warp col base

    // staging maps
    const int prow = tid >> 1, ph = tid & 1;     // rbf: 2 threads/row, 8 halfs each
    const int zrow = tid & 127, zsel = tid >> 7; // z:   128 zi + 128 zj

    // ---- one-time fills ----
    for (int idx = tid; idx < EMB * NRAD; idx += THREADS) {
        int n = idx & 127, k = idx >> 7;
        __half h = __float2half(W_rbf[k * EMB + n]);
        *(unsigned short*)(smem + OFF_BT1 + n * 32 + physmap(k) * 2) = __half_as_ushort(h);
    }
    for (int idx = tid; idx < EMB * EMB; idx += THREADS) {
        int n = idx & 127, k = idx >> 7;
        __half h = __float2half(W[(2 * EMB + k) * EMB + n]);   // W3[k][n]
        int ks = k >> 4, kk = k & 15;
        *(unsigned short*)(smem + OFF_BT2 + ks * 4096 + n * 32 + physmap(kk) * 2) =
            __half_as_ushort(h);
    }
    if (tid < EMB) ((float*)(smem + OFF_BIAS))[tid] = b_rbf[tid];

    // ---- prologue: stage first tile into buffer 0 ----
    int t = blockIdx.x;
    {
        long eb = (long)t * TILE;
        long e  = eb + prow; if (e >= N_EDGES_) e = N_EDGES_ - 1;
        float4 a = ((const float4*)rbf)[e * 4 + 2 * ph];
        float4 b = ((const float4*)rbf)[e * 4 + 2 * ph + 1];
        long ez = eb + zrow; if (ez >= N_EDGES_) ez = N_EDGES_ - 1;
        int pz = Z[(zsel ? idx_j : idx_i)[ez]];
        uint32_t* dst = (uint32_t*)(smem + OFF_RBFH + prow * 32 + ph * 4);
        dst[0] = pack2(a.x, a.y); dst[2] = pack2(a.z, a.w);
        dst[4] = pack2(b.x, b.y); dst[6] = pack2(b.z, b.w);
        ((int*)(smem + (zsel ? OFF_ZJ : OFF_ZI)))[zrow] = pz;
    }
    __syncthreads();

    int buf = 0;
    for (; t < NTILES; t += GRID_MAIN) {
        // ---- prefetch next tile's staging data (hidden under compute) ----
        float4 pa, pb; int pz;
        {
            int tn = t + GRID_MAIN;
            long eb = (long)(tn < NTILES ? tn : t) * TILE;
            long e  = eb + prow; if (e >= N_EDGES_) e = N_EDGES_ - 1;
            pa = ((const float4*)rbf)[e * 4 + 2 * ph];
            pb = ((const float4*)rbf)[e * 4 + 2 * ph + 1];
            long ez = eb + zrow; if (ez >= N_EDGES_) ez = N_EDGES_ - 1;
            pz = Z[(zsel ? idx_j : idx_i)[ez]];
        }

        const long base = (long)t * TILE;
        const char* rb  = smem + OFF_RBFH + buf * 4096;
        const int* zi_s = (const int*)(smem + OFF_ZI + buf * 512);
        const int* zj_s = (const int*)(smem + OFF_ZJ + buf * 512);

        // ---- A operands for GEMM1 (rbf fragments) ----
        uint2 arlo[2], arhi[2];
#pragma unroll
        for (int mt = 0; mt < 2; mt++) {
            int r = m0 + 16 * mt + q;
            arlo[mt] = *(const uint2*)(rb + r * 32 + 8 * c);
            arhi[mt] = *(const uint2*)(rb + (r + 8) * 32 + 8 * c);
        }

        // ---- fused GEMM1 -> silu -> GEMM2, one k-step at a time ----
        float dacc[2][8][4];
#pragma unroll
        for (int mt = 0; mt < 2; mt++)
#pragma unroll
            for (int nt = 0; nt < 8; nt++)
#pragma unroll
                for (int r = 0; r < 4; r++) dacc[mt][nt][r] = 0.0f;

        const float* bias_s = (const float*)(smem + OFF_BIAS);
#pragma unroll
        for (int ks = 0; ks < 8; ks++) {
            uint32_t afrag[2][4];
#pragma unroll
            for (int half = 0; half < 2; half++) {
                int nt1 = 2 * ks + half;
                uint2 bv = *(const uint2*)(smem + OFF_BT1 + (8 * nt1 + q) * 32 + 8 * c);
                float2 bb = *(const float2*)(bias_s + 8 * nt1 + 2 * c);
#pragma unroll
                for (int mt = 0; mt < 2; mt++) {
                    float d[4] = {bb.x, bb.y, bb.x, bb.y};
                    mma_f16(d, arlo[mt].x, arhi[mt].x, arlo[mt].y, arhi[mt].y, bv.x, bv.y);
                    afrag[mt][2 * half]     = pack2(silu_tanh(d[0]), silu_tanh(d[1]));
                    afrag[mt][2 * half + 1] = pack2(silu_tanh(d[2]), silu_tanh(d[3]));
                }
            }
#pragma unroll
            for (int nt = 0; nt < 8; nt++) {
                uint2 bv = *(const uint2*)(smem + OFF_BT2 + ks * 4096 +
                                           (n0 + 8 * nt + q) * 32 + 8 * c);
                mma_f16(dacc[0][nt], afrag[0][0], afrag[0][1], afrag[0][2], afrag[0][3],
                        bv.x, bv.y);
                mma_f16(dacc[1][nt], afrag[1][0], afrag[1][1], afrag[1][2], afrag[1][3],
                        bv.x, bv.y);
            }
        }

        // ---- epilogue: out = silu(D + EW1[zi] + EW2[zj]) ----
#pragma unroll
        for (int mt = 0; mt < 2; mt++) {
#pragma unroll
            for (int sub = 0; sub < 2; sub++) {
                int r = m0 + 16 * mt + 8 * sub + q;
                long e = base + r;
                if (e < N_EDGES_) {
                    int zi = zi_s[r], zj = zj_s[r];
                    const float* p1 = g_EW1 + zi * EMB;
                    const float* p2 = g_EW2 + zj * EMB;
                    float* op = out + (size_t)e * EMB;
#pragma unroll
                    for (int nt = 0; nt < 8; nt++) {
                        int n = n0 + 8 * nt + 2 * c;
                        float2 w1 = *(const float2*)(p1 + n);
                        float2 w2 = *(const float2*)(p2 + n);
                        float2 o;
                        o.x = silu_exact(dacc[mt][nt][2 * sub + 0] + w1.x + w2.x);
                        o.y = silu_exact(dacc[mt][nt][2 * sub + 1] + w1.y + w2.y);
                        *(float2*)(op + n) = o;
                    }
                }
            }
        }

        // ---- store prefetched staging data into the other buffer ----
        {
            int nb = buf ^ 1;
            uint32_t* dst = (uint32_t*)(smem + OFF_RBFH + nb * 4096 + prow * 32 + ph * 4);
            dst[0] = pack2(pa.x, pa.y); dst[2] = pack2(pa.z, pa.w);
            dst[4] = pack2(pb.x, pb.y); dst[6] = pack2(pb.z, pb.w);
            ((int*)(smem + (zsel ? OFF_ZJ : OFF_ZI) + nb * 512))[zrow] = pz;
        }
        __syncthreads();
        buf ^= 1;
    }
}

// ---------------- launch ----------------
extern "C" void kernel_launch(void* const* d_in, const int* in_sizes, int n_in,
                              void* d_out, int out_size) {
    (void)in_sizes; (void)n_in; (void)out_size;
    const int*   Z     = (const int*)d_in[0];
    const float* rbf   = (const float*)d_in[1];
    const int*   idx_i = (const int*)d_in[2];
    const int*   idx_j = (const int*)d_in[3];
    const float* emb   = (const float*)d_in[4];
    const float* W_rbf = (const float*)d_in[5];
    const float* b_rbf = (const float*)d_in[6];
    const float* W     = (const float*)d_in[7];
    const float* b     = (const float*)d_in[8];
    float* out  = (float*)d_out;
    float* out0 = out + (size_t)N_EDGES_ * EMB;

    prep_kernel<<<N_ELEM, 256>>>(emb, W, b);
    x0_kernel<<<(N_ATOMS_ * (EMB / 4) + 255) / 256, 256>>>(Z, emb, out0);
    main_kernel<<<GRID_MAIN, THREADS>>>(Z, rbf, idx_i, idx_j, W_rbf, b_rbf, W, out);
}

// round 7
// speedup vs baseline: 2.8577x; 1.0581x over previous
#include <cuda_runtime.h>
#include <cuda_fp16.h>
#include <cstdint>

#define EMB      128
#define NRAD     16
#define N_ATOMS_ 100000
#define N_EDGES_ 1000000
#define N_ELEM   95
#define TILE     128
#define NTILES   ((N_EDGES_ + TILE - 1) / TILE)   // 7813
#define GRID_MAIN 296
#define THREADS  256

// ---------------- smem layout (bytes) ----------------
#define OFF_BT2   0                    // W3^T fp16 frags [ks(8)][n(128)][16h] = 32KB
#define OFF_BT1   32768                // W_rbf^T fp16 frags [n(128)][16h]     = 4KB
#define OFF_RBFH  36864                // rbf tile fp16 A-frag, x2 buffers     = 8KB
#define OFF_BIAS  45056                // b_rbf [128] f32
#define OFF_ZI    45568                // zi x2 buffers
#define OFF_ZJ    46592                // zj x2 buffers
#define SMEM_TOTAL 47616

__device__ float g_EW1[N_ELEM * EMB];
__device__ float g_EW2[N_ELEM * EMB];

// ---------------- helpers ----------------
__device__ __forceinline__ float silu_tanh(float x) {
    float t;
    asm("tanh.approx.f32 %0, %1;" : "=f"(t) : "f"(0.5f * x));
    return 0.5f * x * (1.0f + t);
}
__device__ __forceinline__ uint32_t pack2(float lo, float hi) {
    uint32_t r;
    asm("cvt.rn.f16x2.f32 %0, %1, %2;" : "=r"(r) : "f"(hi), "f"(lo));
    return r;
}
__device__ __forceinline__ void mma_f16(float* d,
    uint32_t a0, uint32_t a1, uint32_t a2, uint32_t a3,
    uint32_t b0, uint32_t b1) {
    asm volatile(
        "mma.sync.aligned.m16n8k16.row.col.f32.f16.f16.f32 "
        "{%0,%1,%2,%3}, {%4,%5,%6,%7}, {%8,%9}, {%0,%1,%2,%3};"
        : "+f"(d[0]), "+f"(d[1]), "+f"(d[2]), "+f"(d[3])
        : "r"(a0), "r"(a1), "r"(a2), "r"(a3), "r"(b0), "r"(b1));
}
// physical half position inside a 16-half (32B) chunk so thread c's uint2 at
// byte 8c holds halfs {2c, 2c+1, 2c+8, 2c+9} (== mma fragment pairs)
__device__ __forceinline__ int physmap(int kk) {
    return 4 * ((kk & 7) >> 1) + 2 * (kk >> 3) + (kk & 1);
}

// ---------------- precompute: EW1 = emb@W1 + b, EW2 = emb@W2 ----------------
__global__ void prep_kernel(const float* __restrict__ emb, const float* __restrict__ W,
                            const float* __restrict__ b) {
    __shared__ float p1[EMB], p2[EMB];
    int z = blockIdx.x, n = threadIdx.x & 127, h = threadIdx.x >> 7;
    const float* er = emb + z * EMB;
    float s1 = 0.0f, s2 = 0.0f;
    int k0 = h * 64;
#pragma unroll 8
    for (int k = k0; k < k0 + 64; k++) {
        float ev = er[k];
        s1 += ev * W[k * EMB + n];
        s2 += ev * W[(EMB + k) * EMB + n];
    }
    if (h) { p1[n] = s1; p2[n] = s2; }
    __syncthreads();
    if (!h) {
        g_EW1[z * EMB + n] = s1 + p1[n] + b[n];
        g_EW2[z * EMB + n] = s2 + p2[n];
    }
}

// ---------------- main fused edge kernel (also does x_0 copy) ----------------
__global__ void __launch_bounds__(THREADS, 2)
main_kernel(const int* __restrict__ Z, const float* __restrict__ rbf,
            const int* __restrict__ idx_i, const int* __restrict__ idx_j,
            const float* __restrict__ W_rbf, const float* __restrict__ b_rbf,
            const float* __restrict__ W, float* __restrict__ out,
            const float* __restrict__ emb, float* __restrict__ out0) {
    __shared__ char smem[SMEM_TOTAL];
    const int tid  = threadIdx.x;
    const int wid  = tid >> 5, lane = tid & 31;
    const int q    = lane >> 2, c = lane & 3;
    const int m0   = wid * 16;           // warp owns 16 rows, all 128 cols

    // staging maps
    const int prow = tid >> 1, ph = tid & 1;     // rbf: 2 threads/row
    const int zrow = tid & 127, zsel = tid >> 7; // z: 128 zi + 128 zj

    // ---- x_0 = embeddings[Z] (independent; overlaps smem fills) ----
    for (int i = blockIdx.x * THREADS + tid; i < N_ATOMS_ * (EMB / 4);
         i += GRID_MAIN * THREADS) {
        int a = i >> 5, qq = i & 31;
        ((float4*)out0)[(size_t)a * 32 + qq] = ((const float4*)emb)[(size_t)Z[a] * 32 + qq];
    }

    // ---- one-time fills ----
    for (int idx = tid; idx < EMB * NRAD; idx += THREADS) {
        int n = idx & 127, k = idx >> 7;
        __half h = __float2half(W_rbf[k * EMB + n]);
        *(unsigned short*)(smem + OFF_BT1 + n * 32 + physmap(k) * 2) = __half_as_ushort(h);
    }
    for (int idx = tid; idx < EMB * EMB; idx += THREADS) {
        int n = idx & 127, k = idx >> 7;
        __half h = __float2half(W[(2 * EMB + k) * EMB + n]);   // W3[k][n]
        int ks = k >> 4, kk = k & 15;
        *(unsigned short*)(smem + OFF_BT2 + ks * 4096 + n * 32 + physmap(kk) * 2) =
            __half_as_ushort(h);
    }
    if (tid < EMB) ((float*)(smem + OFF_BIAS))[tid] = b_rbf[tid];

    // ---- prologue: stage first tile into buffer 0 ----
    int t = blockIdx.x;
    {
        long eb = (long)t * TILE;
        long e  = eb + prow; if (e >= N_EDGES_) e = N_EDGES_ - 1;
        float4 a = ((const float4*)rbf)[e * 4 + 2 * ph];
        float4 b = ((const float4*)rbf)[e * 4 + 2 * ph + 1];
        long ez = eb + zrow; if (ez >= N_EDGES_) ez = N_EDGES_ - 1;
        int pz = Z[(zsel ? idx_j : idx_i)[ez]];
        uint32_t* dst = (uint32_t*)(smem + OFF_RBFH + prow * 32 + ph * 4);
        dst[0] = pack2(a.x, a.y); dst[2] = pack2(a.z, a.w);
        dst[4] = pack2(b.x, b.y); dst[6] = pack2(b.z, b.w);
        ((int*)(smem + (zsel ? OFF_ZJ : OFF_ZI)))[zrow] = pz;
    }
    __syncthreads();

    int buf = 0;
    for (; t < NTILES; t += GRID_MAIN) {
        // ---- prefetch next tile's staging data ----
        float4 pa, pb; int pz;
        {
            int tn = t + GRID_MAIN;
            long eb = (long)(tn < NTILES ? tn : t) * TILE;
            long e  = eb + prow; if (e >= N_EDGES_) e = N_EDGES_ - 1;
            pa = ((const float4*)rbf)[e * 4 + 2 * ph];
            pb = ((const float4*)rbf)[e * 4 + 2 * ph + 1];
            long ez = eb + zrow; if (ez >= N_EDGES_) ez = N_EDGES_ - 1;
            pz = Z[(zsel ? idx_j : idx_i)[ez]];
        }

        const long base = (long)t * TILE;
        const char* rb  = smem + OFF_RBFH + buf * 4096;
        const int* zi_s = (const int*)(smem + OFF_ZI + buf * 512);
        const int* zj_s = (const int*)(smem + OFF_ZJ + buf * 512);

        // ---- A operands for GEMM1 (this warp's 16 rows only) ----
        uint2 arlo = *(const uint2*)(rb + (m0 + q) * 32 + 8 * c);
        uint2 arhi = *(const uint2*)(rb + (m0 + 8 + q) * 32 + 8 * c);

        // ---- fused GEMM1 -> silu -> GEMM2, one k-step at a time ----
        float dacc[16][4];
#pragma unroll
        for (int nt = 0; nt < 16; nt++)
#pragma unroll
            for (int r = 0; r < 4; r++) dacc[nt][r] = 0.0f;

        const float* bias_s = (const float*)(smem + OFF_BIAS);
#pragma unroll
        for (int ks = 0; ks < 8; ks++) {
            uint32_t afrag[4];
#pragma unroll
            for (int half = 0; half < 2; half++) {
                int nt1 = 2 * ks + half;
                uint2 bv = *(const uint2*)(smem + OFF_BT1 + (8 * nt1 + q) * 32 + 8 * c);
                float2 bb = *(const float2*)(bias_s + 8 * nt1 + 2 * c);
                float d[4] = {bb.x, bb.y, bb.x, bb.y};
                mma_f16(d, arlo.x, arhi.x, arlo.y, arhi.y, bv.x, bv.y);
                afrag[2 * half]     = pack2(silu_tanh(d[0]), silu_tanh(d[1]));
                afrag[2 * half + 1] = pack2(silu_tanh(d[2]), silu_tanh(d[3]));
            }
#pragma unroll
            for (int nt = 0; nt < 16; nt++) {
                uint2 bv = *(const uint2*)(smem + OFF_BT2 + ks * 4096 +
                                           (8 * nt + q) * 32 + 8 * c);
                mma_f16(dacc[nt], afrag[0], afrag[1], afrag[2], afrag[3], bv.x, bv.y);
            }
        }

        // ---- epilogue: out = silu(D + EW1[zi] + EW2[zj]) ----
#pragma unroll
        for (int sub = 0; sub < 2; sub++) {
            int r = m0 + 8 * sub + q;
            long e = base + r;
            if (e < N_EDGES_) {
                int zi = zi_s[r], zj = zj_s[r];
                const float* p1 = g_EW1 + zi * EMB;
                const float* p2 = g_EW2 + zj * EMB;
                float* op = out + (size_t)e * EMB;
#pragma unroll
                for (int nt = 0; nt < 16; nt++) {
                    int n = 8 * nt + 2 * c;
                    float2 w1 = *(const float2*)(p1 + n);
                    float2 w2 = *(const float2*)(p2 + n);
                    float2 o;
                    o.x = silu_tanh(dacc[nt][2 * sub + 0] + w1.x + w2.x);
                    o.y = silu_tanh(dacc[nt][2 * sub + 1] + w1.y + w2.y);
                    *(float2*)(op + n) = o;
                }
            }
        }

        // ---- store prefetched staging data into the other buffer ----
        {
            int nb = buf ^ 1;
            uint32_t* dst = (uint32_t*)(smem + OFF_RBFH + nb * 4096 + prow * 32 + ph * 4);
            dst[0] = pack2(pa.x, pa.y); dst[2] = pack2(pa.z, pa.w);
            dst[4] = pack2(pb.x, pb.y); dst[6] = pack2(pb.z, pb.w);
            ((int*)(smem + (zsel ? OFF_ZJ : OFF_ZI) + nb * 512))[zrow] = pz;
        }
        __syncthreads();
        buf ^= 1;
    }
}

// ---------------- launch ----------------
extern "C" void kernel_launch(void* const* d_in, const int* in_sizes, int n_in,
                              void* d_out, int out_size) {
    (void)in_sizes; (void)n_in; (void)out_size;
    const int*   Z     = (const int*)d_in[0];
    const float* rbf   = (const float*)d_in[1];
    const int*   idx_i = (const int*)d_in[2];
    const int*   idx_j = (const int*)d_in[3];
    const float* emb   = (const float*)d_in[4];
    const float* W_rbf = (const float*)d_in[5];
    const float* b_rbf = (const float*)d_in[6];
    const float* W     = (const float*)d_in[7];
    const float* b     = (const float*)d_in[8];
    float* out  = (float*)d_out;
    float* out0 = out + (size_t)N_EDGES_ * EMB;

    prep_kernel<<<N_ELEM, 256>>>(emb, W, b);
    main_kernel<<<GRID_MAIN, THREADS>>>(Z, rbf, idx_i, idx_j, W_rbf, b_rbf, W, out,
                                        emb, out0);
}